// round 2
// baseline (speedup 1.0000x reference)
#include <cuda_runtime.h>
#include <math.h>
#include <stdint.h>

// Problem constants (from reference): N=50000, E=500000, F=32, H=4, C=64,
// NHID=NOUT=256, B=1000. Self loops appended -> E2 = E + N.
#define MAXN 50000
#define MAXE 500000
#define MAXE2 (MAXN + MAXE)
#define HMAX 4
#define HC_MAX 256
#define BMAX 1000

// ---------------- scratch (static device globals; no allocation) -----------
static __device__ __align__(16) float g_bufA[(size_t)MAXN * HC_MAX]; // gemm out h_lin
static __device__ __align__(16) float g_bufB[(size_t)MAXN * HC_MAX]; // aggregated out
static __device__ float g_als[(size_t)MAXN * HMAX];
static __device__ float g_ald[(size_t)MAXN * HMAX];
static __device__ float g_m[(size_t)MAXN * HMAX];
static __device__ float g_z[(size_t)MAXN * HMAX];
static __device__ float g_e[(size_t)MAXE2 * HMAX];       // per-edge logits -> p
static __device__ __align__(16) float g_xg[(size_t)BMAX * 64];
static __device__ float g_cnt[BMAX];
static __device__ float g_y1[(size_t)BMAX * 256];
static __device__ float g_y2[(size_t)BMAX * 256];
static __device__ int   g_src[MAXE];
static __device__ int   g_dst[MAXE];
static __device__ int   g_batch[MAXN];
static __device__ int   g_is64;   // 1 if raw index buffers are int64, 0 if int32

// ---------------- helpers ---------------------------------------------------
static inline int cdiv(long long a, long long b) { return (int)((a + b - 1) / b); }

__device__ __forceinline__ void atomicMaxFloat(float* addr, float v) {
    if (v >= 0.f) atomicMax((int*)addr, __float_as_int(v));
    else          atomicMin((unsigned int*)addr, (unsigned int)__float_as_int(v));
}

// ---------------- dtype probe + index conversion ----------------------------

// Single-thread probe: if the first elements viewed as int64 are valid node
// indices, the buffer really is int64; otherwise it is int32 (an int64 view of
// packed int32 pairs puts a random index in the high word -> out of range).
__global__ void detect_dtype(const void* ei_raw, int E, int N) {
    const long long* p = (const long long*)ei_raw;
    int k = E < 256 ? E : 256;   // reads only first 2KB: safe for both dtypes
    int ok = 1;
    for (int i = 0; i < k; i++) {
        long long v = p[i];
        if (v < 0 || v >= N) { ok = 0; break; }
    }
    g_is64 = ok;
}

__global__ void convert_ei(const void* ei_raw, int* __restrict__ src,
                           int* __restrict__ dst, int E) {
    int i = blockIdx.x * blockDim.x + threadIdx.x;
    if (i >= E) return;
    if (g_is64) {
        const long long* p = (const long long*)ei_raw;
        src[i] = (int)p[i];
        dst[i] = (int)p[E + i];
    } else {
        const int* p = (const int*)ei_raw;
        src[i] = p[i];
        dst[i] = p[E + i];
    }
}

__global__ void convert_batch(const void* b_raw, int* __restrict__ out, int N) {
    int i = blockIdx.x * blockDim.x + threadIdx.x;
    if (i >= N) return;
    if (g_is64) out[i] = (int)((const long long*)b_raw)[i];
    else        out[i] = ((const int*)b_raw)[i];
}

// ---------------- kernels ---------------------------------------------------

__global__ void fill_kernel(float* __restrict__ p, float v, int n) {
    int i = blockIdx.x * blockDim.x + threadIdx.x;
    if (i < n) p[i] = v;
}

// out[N,Fout] = X[N,Fin] @ W[Fin,Fout]. blockDim.x == Fout. TM rows per block.
template <int TM>
__global__ void gemm_kernel(const float* __restrict__ X, const float* __restrict__ W,
                            float* __restrict__ out, int N, int Fin, int Fout) {
    extern __shared__ float sx[]; // TM * Fin
    int j = threadIdx.x;
    int n0 = blockIdx.x * TM;
    int total = TM * Fin;
    for (int i = j; i < total; i += blockDim.x) {
        int r = i / Fin, c = i - r * Fin;
        int n = n0 + r;
        sx[i] = (n < N) ? X[(size_t)n * Fin + c] : 0.f;
    }
    __syncthreads();
    float acc[TM];
#pragma unroll
    for (int i = 0; i < TM; i++) acc[i] = 0.f;
    for (int k = 0; k < Fin; k++) {
        float w = __ldg(&W[(size_t)k * Fout + j]);
#pragma unroll
        for (int i = 0; i < TM; i++) acc[i] += sx[i * Fin + k] * w;
    }
#pragma unroll
    for (int i = 0; i < TM; i++) {
        int n = n0 + i;
        if (n < N) out[(size_t)n * Fout + j] = acc[i];
    }
}

// als[n,h] = dot(h[n,h,:], a_src[h,:]); ald likewise. One warp per (n,h).
__global__ void attn_logits(const float* __restrict__ h, const float* __restrict__ a_src,
                            const float* __restrict__ a_dst,
                            float* __restrict__ als, float* __restrict__ ald,
                            int N, int Hn, int Cn) {
    int wid = (blockIdx.x * blockDim.x + threadIdx.x) >> 5;
    int lane = threadIdx.x & 31;
    if (wid >= N * Hn) return;
    int n = wid / Hn, hh = wid - n * Hn;
    const float* row = h + (size_t)n * Hn * Cn + hh * Cn;
    float s = 0.f, d = 0.f;
    for (int c = lane; c < Cn; c += 32) {
        float v = row[c];
        s += v * a_src[hh * Cn + c];
        d += v * a_dst[hh * Cn + c];
    }
#pragma unroll
    for (int o = 16; o > 0; o >>= 1) {
        s += __shfl_down_sync(0xFFFFFFFFu, s, o);
        d += __shfl_down_sync(0xFFFFFFFFu, d, o);
    }
    if (lane == 0) { als[wid] = s; ald[wid] = d; }
}

__device__ __forceinline__ void edge_src_dst(const int* __restrict__ srcA,
                                             const int* __restrict__ dstA,
                                             int eid, int E, int& src, int& dst) {
    if (eid < E) { src = srcA[eid]; dst = dstA[eid]; }
    else { src = dst = eid - E; }   // appended self loops
}

// pass 1: e = leaky_relu(als[src]+ald[dst], 0.2); atomic max into m[dst]
__global__ void edge_logits_max(const int* __restrict__ srcA, const int* __restrict__ dstA,
                                const float* __restrict__ als, const float* __restrict__ ald,
                                float* __restrict__ ebuf, float* __restrict__ m,
                                int E, int N, int Hn) {
    int t = blockIdx.x * blockDim.x + threadIdx.x;
    int total = (E + N) * Hn;
    if (t >= total) return;
    int eid = t / Hn, hh = t - eid * Hn;
    int src, dst; edge_src_dst(srcA, dstA, eid, E, src, dst);
    float v = als[src * Hn + hh] + ald[dst * Hn + hh];
    v = (v > 0.f) ? v : 0.2f * v;
    ebuf[t] = v;
    atomicMaxFloat(&m[dst * Hn + hh], v);
}

// pass 2: p = exp(e - m[dst]); atomicAdd into z[dst]
__global__ void edge_exp_sum(const int* __restrict__ srcA, const int* __restrict__ dstA,
                             const float* __restrict__ m,
                             float* __restrict__ ebuf, float* __restrict__ z,
                             int E, int N, int Hn) {
    int t = blockIdx.x * blockDim.x + threadIdx.x;
    int total = (E + N) * Hn;
    if (t >= total) return;
    int eid = t / Hn, hh = t - eid * Hn;
    int src, dst; edge_src_dst(srcA, dstA, eid, E, src, dst);
    (void)src;
    float p = expf(ebuf[t] - m[dst * Hn + hh]);
    ebuf[t] = p;
    atomicAdd(&z[dst * Hn + hh], p);
}

// pass 3: out[dst] += (p/z[dst]) * h[src]. One float4 per thread.
__global__ void edge_aggregate(const int* __restrict__ srcA, const int* __restrict__ dstA,
                               const float* __restrict__ hlin,
                               const float* __restrict__ ebuf, const float* __restrict__ z,
                               float* __restrict__ out,
                               int E, int N, int Hn, int Cn) {
    int qpe = (Hn * Cn) >> 2;                      // float4 quads per edge
    long long t = (long long)blockIdx.x * blockDim.x + threadIdx.x;
    long long total = (long long)(E + N) * qpe;
    if (t >= total) return;
    int eid = (int)(t / qpe);
    int q = (int)(t - (long long)eid * qpe);
    int hh = q / (Cn >> 2);
    int src, dst; edge_src_dst(srcA, dstA, eid, E, src, dst);
    float p = ebuf[eid * Hn + hh];
    float zz = z[dst * Hn + hh];
    float coef = p / (zz + 1e-16f);
    const float4 v = ((const float4*)(hlin + (size_t)src * Hn * Cn))[q];
    float4 r; r.x = v.x * coef; r.y = v.y * coef; r.z = v.z * coef; r.w = v.w * coef;
    atomicAdd(((float4*)(out + (size_t)dst * Hn * Cn)) + q, r);  // sm_90+: vector red
}

__global__ void bias_act(float* __restrict__ x, const float* __restrict__ b,
                         int N, int Fout, int relu) {
    int t = blockIdx.x * blockDim.x + threadIdx.x;
    if (t >= N * Fout) return;
    int j = t % Fout;
    float v = x[t] + b[j];
    if (relu) v = fmaxf(v, 0.f);
    x[t] = v;
}

__global__ void pool_kernel(const float* __restrict__ h3, const int* __restrict__ batch,
                            float* __restrict__ xg, float* __restrict__ cnt, int N, int Cn) {
    int t = blockIdx.x * blockDim.x + threadIdx.x;
    if (t >= N * Cn) return;
    int n = t / Cn, c = t - n * Cn;
    int b = batch[n];
    atomicAdd(&xg[b * Cn + c], h3[t]);
    if (c == 0) atomicAdd(&cnt[b], 1.f);
}

__global__ void pool_div(float* __restrict__ xg, const float* __restrict__ cnt, int B, int Cn) {
    int t = blockIdx.x * blockDim.x + threadIdx.x;
    if (t >= B * Cn) return;
    int b = t / Cn;
    xg[t] /= fmaxf(cnt[b], 1.f);
}

// y = LN(y + bias) * g + be ; one block (256 threads) per row, Fn == 256.
__global__ void bias_ln(const float* __restrict__ y, const float* __restrict__ bias,
                        const float* __restrict__ g, const float* __restrict__ be,
                        float* __restrict__ out, int Fn) {
    __shared__ float red[256];
    int b = blockIdx.x, j = threadIdx.x;
    float v = y[(size_t)b * Fn + j] + bias[j];
    red[j] = v; __syncthreads();
#pragma unroll
    for (int s = 128; s > 0; s >>= 1) { if (j < s) red[j] += red[j + s]; __syncthreads(); }
    float mu = red[0] * (1.f / 256.f);
    __syncthreads();
    float dv = v - mu;
    red[j] = dv * dv; __syncthreads();
#pragma unroll
    for (int s = 128; s > 0; s >>= 1) { if (j < s) red[j] += red[j + s]; __syncthreads(); }
    float var = red[0] * (1.f / 256.f);
    out[(size_t)b * Fn + j] = dv * rsqrtf(var + 1e-5f) * g[j] + be[j];
}

// ---------------- host orchestration ---------------------------------------

static void gat_layer(const float* Xin, int Fin, int Hn, int Cn,
                      const float* W, const float* asrc, const float* adst, const float* bias,
                      int relu, const int* srcA, const int* dstA, int N, int E,
                      float* hlin, float* outagg,
                      float* als, float* ald, float* m, float* z, float* ebuf) {
    int Fout = Hn * Cn;
    gemm_kernel<8><<<cdiv(N, 8), Fout, 8 * Fin * sizeof(float)>>>(Xin, W, hlin, N, Fin, Fout);
    attn_logits<<<cdiv((long long)N * Hn * 32, 256), 256>>>(hlin, asrc, adst, als, ald, N, Hn, Cn);
    fill_kernel<<<cdiv(N * Hn, 256), 256>>>(m, -INFINITY, N * Hn);
    cudaMemsetAsync(z, 0, (size_t)N * Hn * sizeof(float));
    cudaMemsetAsync(outagg, 0, (size_t)N * Fout * sizeof(float));
    int tot = (E + N) * Hn;
    edge_logits_max<<<cdiv(tot, 256), 256>>>(srcA, dstA, als, ald, ebuf, m, E, N, Hn);
    edge_exp_sum<<<cdiv(tot, 256), 256>>>(srcA, dstA, m, ebuf, z, E, N, Hn);
    long long tot3 = (long long)(E + N) * (Fout >> 2);
    edge_aggregate<<<cdiv(tot3, 256), 256>>>(srcA, dstA, hlin, ebuf, z, outagg, E, N, Hn, Cn);
    bias_act<<<cdiv(N * Fout, 256), 256>>>(outagg, bias, N, Fout, relu);
}

extern "C" void kernel_launch(void* const* d_in, const int* in_sizes, int n_in,
                              void* d_out, int out_size) {
    const float* x      = (const float*)d_in[0];
    const void*  ei_raw = d_in[1];
    const void*  b_raw  = d_in[2];
    const float* W1   = (const float*)d_in[3];
    const float* as1  = (const float*)d_in[4];
    const float* ad1  = (const float*)d_in[5];
    const float* b1   = (const float*)d_in[6];
    const float* W2   = (const float*)d_in[7];
    const float* as2  = (const float*)d_in[8];
    const float* ad2  = (const float*)d_in[9];
    const float* b2   = (const float*)d_in[10];
    const float* W3   = (const float*)d_in[11];
    const float* as3  = (const float*)d_in[12];
    const float* ad3  = (const float*)d_in[13];
    const float* b3   = (const float*)d_in[14];
    const float* Wm1  = (const float*)d_in[15];
    const float* bm1  = (const float*)d_in[16];
    const float* Wm2  = (const float*)d_in[17];
    const float* bm2  = (const float*)d_in[18];
    const float* g2   = (const float*)d_in[19];
    const float* be2  = (const float*)d_in[20];

    int N = in_sizes[0] / 32;
    int E = in_sizes[1] / 2;
    int B = out_size / 256;

    float *bufA, *bufB, *als, *ald, *m, *z, *ebuf, *xg, *cnt, *y1, *y2;
    int *srcA, *dstA, *batch;
    cudaGetSymbolAddress((void**)&bufA, g_bufA);
    cudaGetSymbolAddress((void**)&bufB, g_bufB);
    cudaGetSymbolAddress((void**)&als,  g_als);
    cudaGetSymbolAddress((void**)&ald,  g_ald);
    cudaGetSymbolAddress((void**)&m,    g_m);
    cudaGetSymbolAddress((void**)&z,    g_z);
    cudaGetSymbolAddress((void**)&ebuf, g_e);
    cudaGetSymbolAddress((void**)&xg,   g_xg);
    cudaGetSymbolAddress((void**)&cnt,  g_cnt);
    cudaGetSymbolAddress((void**)&y1,   g_y1);
    cudaGetSymbolAddress((void**)&y2,   g_y2);
    cudaGetSymbolAddress((void**)&srcA, g_src);
    cudaGetSymbolAddress((void**)&dstA, g_dst);
    cudaGetSymbolAddress((void**)&batch, g_batch);

    // Normalize index dtypes (int64 vs int32) into int32 scratch.
    detect_dtype<<<1, 1>>>(ei_raw, E, N);
    convert_ei<<<cdiv(E, 256), 256>>>(ei_raw, srcA, dstA, E);
    convert_batch<<<cdiv(N, 256), 256>>>(b_raw, batch, N);

    // conv1: F=32 -> 4x64, relu
    gat_layer(x,    32, 4, 64, W1, as1, ad1, b1, 1, srcA, dstA, N, E, bufA, bufB, als, ald, m, z, ebuf);
    // conv2: 256 -> 4x64, relu
    gat_layer(bufB, 256, 4, 64, W2, as2, ad2, b2, 1, srcA, dstA, N, E, bufA, bufB, als, ald, m, z, ebuf);
    // conv3: 256 -> 1x64, no relu
    gat_layer(bufB, 256, 1, 64, W3, as3, ad3, b3, 0, srcA, dstA, N, E, bufA, bufB, als, ald, m, z, ebuf);

    // global mean pool over batch
    cudaMemsetAsync(xg, 0, (size_t)B * 64 * sizeof(float));
    cudaMemsetAsync(cnt, 0, (size_t)B * sizeof(float));
    pool_kernel<<<cdiv((long long)N * 64, 256), 256>>>(bufB, batch, xg, cnt, N, 64);
    pool_div<<<cdiv(B * 64, 256), 256>>>(xg, cnt, B, 64);

    // MLP head: relu(xg @ Wm1 + bm1) @ Wm2 + bm2 -> LayerNorm
    gemm_kernel<8><<<cdiv(B, 8), 256, 8 * 64 * sizeof(float)>>>(xg, Wm1, y1, B, 64, 256);
    bias_act<<<cdiv(B * 256, 256), 256>>>(y1, bm1, B, 256, 1);
    gemm_kernel<8><<<cdiv(B, 8), 256, 8 * 256 * sizeof(float)>>>(y1, Wm2, y2, B, 256, 256);
    bias_ln<<<B, 256>>>(y2, bm2, g2, be2, (float*)d_out, 256);
}

// round 3
// speedup vs baseline: 1.1764x; 1.1764x over previous
#include <cuda_runtime.h>
#include <math.h>
#include <stdint.h>

#define MAXN 50000
#define MAXE 500000
#define MAXE2 (MAXN + MAXE)
#define HMAX 4
#define HC_MAX 256
#define BMAX 1000

// ---------------- scratch ----------------------------------------------------
static __device__ __align__(16) float g_bufA[(size_t)MAXN * HC_MAX];
static __device__ __align__(16) float g_bufB[(size_t)MAXN * HC_MAX];
static __device__ float g_als[(size_t)MAXN * HMAX];
static __device__ float g_ald[(size_t)MAXN * HMAX];
static __device__ float g_m[(size_t)MAXN * HMAX];
static __device__ float g_z[(size_t)MAXN * HMAX];
static __device__ float g_e[(size_t)MAXE2 * HMAX];
static __device__ __align__(16) float g_xg[(size_t)BMAX * 64];
static __device__ float g_cnt[BMAX];
static __device__ __align__(16) float g_y1[(size_t)BMAX * 256];
static __device__ __align__(16) float g_y2[(size_t)BMAX * 256];
static __device__ int   g_src[MAXE];
static __device__ int   g_dst[MAXE];
static __device__ int   g_batch[MAXN];
static __device__ int   g_is64;

static inline int cdiv(long long a, long long b) { return (int)((a + b - 1) / b); }

__device__ __forceinline__ void atomicMaxFloat(float* addr, float v) {
    if (v >= 0.f) atomicMax((int*)addr, __float_as_int(v));
    else          atomicMin((unsigned int*)addr, (unsigned int)__float_as_int(v));
}

// ---------------- dtype probe + index conversion ----------------------------
__global__ void detect_dtype(const void* ei_raw, int E, int N) {
    const long long* p = (const long long*)ei_raw;
    int k = E < 256 ? E : 256;
    int ok = 1;
    for (int i = 0; i < k; i++) {
        long long v = p[i];
        if (v < 0 || v >= N) { ok = 0; break; }
    }
    g_is64 = ok;
}

__global__ void convert_ei(const void* ei_raw, int* __restrict__ src,
                           int* __restrict__ dst, int E) {
    int i = blockIdx.x * blockDim.x + threadIdx.x;
    if (i >= E) return;
    if (g_is64) {
        const long long* p = (const long long*)ei_raw;
        src[i] = (int)p[i];
        dst[i] = (int)p[E + i];
    } else {
        const int* p = (const int*)ei_raw;
        src[i] = p[i];
        dst[i] = p[E + i];
    }
}

__global__ void convert_batch(const void* b_raw, int* __restrict__ out, int N) {
    int i = blockIdx.x * blockDim.x + threadIdx.x;
    if (i >= N) return;
    if (g_is64) out[i] = (int)((const long long*)b_raw)[i];
    else        out[i] = ((const int*)b_raw)[i];
}

// ---------------- tiled SGEMM ------------------------------------------------
// out[N,Fout] = act(X + abias)[N,Fin] @ W[Fin,Fout]
// BM=128, BN=64, BK=16, thread tile 8x4, 256 threads.
// abias (len Fin) + arelu are fused into the A-tile load (epilogue of the
// PREVIOUS layer). Requires Fin % 16 == 0, Fout % 64 == 0.
template <int BM, int BN, int BK, int TM, int TN>
__global__ void sgemm_kernel(const float* __restrict__ X, const float* __restrict__ W,
                             float* __restrict__ out, int N, int Fin, int Fout,
                             const float* __restrict__ abias, int arelu) {
    __shared__ float As[BK][BM];    // A transposed
    __shared__ float Bs[BK][BN];
    const int tx = threadIdx.x;
    const int n0 = blockIdx.x * BM;
    const int j0 = blockIdx.y * BN;
    const int tcol = tx % (BN / TN);   // 0..15
    const int trow = tx / (BN / TN);   // 0..15
    float acc[TM][TN];
#pragma unroll
    for (int i = 0; i < TM; i++)
#pragma unroll
        for (int j = 0; j < TN; j++) acc[i][j] = 0.f;

    for (int k0 = 0; k0 < Fin; k0 += BK) {
        // A tile: BM x BK, stored transposed. BM*BK/4 float4 loads.
#pragma unroll
        for (int i = tx; i < BM * BK / 4; i += 256) {
            int r  = i / (BK / 4);
            int c4 = i % (BK / 4);
            int n  = n0 + r;
            float4 v = make_float4(0.f, 0.f, 0.f, 0.f);
            if (n < N) {
                v = *(const float4*)&X[(size_t)n * Fin + k0 + c4 * 4];
                if (abias) {
                    const float4 b = *(const float4*)&abias[k0 + c4 * 4];
                    v.x += b.x; v.y += b.y; v.z += b.z; v.w += b.w;
                    if (arelu) {
                        v.x = fmaxf(v.x, 0.f); v.y = fmaxf(v.y, 0.f);
                        v.z = fmaxf(v.z, 0.f); v.w = fmaxf(v.w, 0.f);
                    }
                }
            }
            As[c4 * 4 + 0][r] = v.x;
            As[c4 * 4 + 1][r] = v.y;
            As[c4 * 4 + 2][r] = v.z;
            As[c4 * 4 + 3][r] = v.w;
        }
        // B tile: BK x BN
#pragma unroll
        for (int i = tx; i < BK * BN / 4; i += 256) {
            int r  = i / (BN / 4);
            int c4 = i % (BN / 4);
            *(float4*)&Bs[r][c4 * 4] =
                *(const float4*)&W[(size_t)(k0 + r) * Fout + j0 + c4 * 4];
        }
        __syncthreads();
#pragma unroll
        for (int k = 0; k < BK; k++) {
            float a[TM], b[TN];
#pragma unroll
            for (int i = 0; i < TM; i++) a[i] = As[k][trow * TM + i];
#pragma unroll
            for (int j = 0; j < TN; j++) b[j] = Bs[k][tcol * TN + j];
#pragma unroll
            for (int i = 0; i < TM; i++)
#pragma unroll
                for (int j = 0; j < TN; j++) acc[i][j] += a[i] * b[j];
        }
        __syncthreads();
    }
#pragma unroll
    for (int i = 0; i < TM; i++) {
        int n = n0 + trow * TM + i;
        if (n >= N) continue;
#pragma unroll
        for (int j4 = 0; j4 < TN / 4; j4++) {
            float4 v = make_float4(acc[i][j4 * 4 + 0], acc[i][j4 * 4 + 1],
                                   acc[i][j4 * 4 + 2], acc[i][j4 * 4 + 3]);
            *(float4*)&out[(size_t)n * Fout + j0 + tcol * TN + j4 * 4] = v;
        }
    }
}

static void launch_sgemm(const float* X, const float* W, float* out,
                         int N, int Fin, int Fout, const float* abias, int arelu) {
    dim3 grid(cdiv(N, 128), Fout / 64);
    sgemm_kernel<128, 64, 16, 8, 4><<<grid, 256>>>(X, W, out, N, Fin, Fout, abias, arelu);
}

// ---------------- misc kernels ----------------------------------------------
__global__ void fill_kernel(float* __restrict__ p, float v, int n) {
    int i = blockIdx.x * blockDim.x + threadIdx.x;
    if (i < n) p[i] = v;
}

__global__ void attn_logits(const float* __restrict__ h, const float* __restrict__ a_src,
                            const float* __restrict__ a_dst,
                            float* __restrict__ als, float* __restrict__ ald,
                            int N, int Hn, int Cn) {
    int wid = (blockIdx.x * blockDim.x + threadIdx.x) >> 5;
    int lane = threadIdx.x & 31;
    if (wid >= N * Hn) return;
    int n = wid / Hn, hh = wid - n * Hn;
    const float* row = h + (size_t)n * Hn * Cn + hh * Cn;
    float s = 0.f, d = 0.f;
    for (int c = lane; c < Cn; c += 32) {
        float v = row[c];
        s += v * a_src[hh * Cn + c];
        d += v * a_dst[hh * Cn + c];
    }
#pragma unroll
    for (int o = 16; o > 0; o >>= 1) {
        s += __shfl_down_sync(0xFFFFFFFFu, s, o);
        d += __shfl_down_sync(0xFFFFFFFFu, d, o);
    }
    if (lane == 0) { als[wid] = s; ald[wid] = d; }
}

__device__ __forceinline__ void edge_src_dst(const int* __restrict__ srcA,
                                             const int* __restrict__ dstA,
                                             int eid, int E, int& src, int& dst) {
    if (eid < E) { src = srcA[eid]; dst = dstA[eid]; }
    else { src = dst = eid - E; }
}

__global__ void edge_logits_max(const int* __restrict__ srcA, const int* __restrict__ dstA,
                                const float* __restrict__ als, const float* __restrict__ ald,
                                float* __restrict__ ebuf, float* __restrict__ m,
                                int E, int N, int Hn) {
    int t = blockIdx.x * blockDim.x + threadIdx.x;
    int total = (E + N) * Hn;
    if (t >= total) return;
    int eid = t / Hn, hh = t - eid * Hn;
    int src, dst; edge_src_dst(srcA, dstA, eid, E, src, dst);
    float v = als[src * Hn + hh] + ald[dst * Hn + hh];
    v = (v > 0.f) ? v : 0.2f * v;
    ebuf[t] = v;
    atomicMaxFloat(&m[dst * Hn + hh], v);
}

__global__ void edge_exp_sum(const int* __restrict__ dstA,
                             const float* __restrict__ m,
                             float* __restrict__ ebuf, float* __restrict__ z,
                             int E, int N, int Hn) {
    int t = blockIdx.x * blockDim.x + threadIdx.x;
    int total = (E + N) * Hn;
    if (t >= total) return;
    int eid = t / Hn, hh = t - eid * Hn;
    int dst = (eid < E) ? dstA[eid] : eid - E;
    float p = expf(ebuf[t] - m[dst * Hn + hh]);
    ebuf[t] = p;
    atomicAdd(&z[dst * Hn + hh], p);
}

// One thread per (edge, head): loads indices/coef once, 16 float4 gather+RED.128
__global__ void edge_aggregate(const int* __restrict__ srcA, const int* __restrict__ dstA,
                               const float* __restrict__ hlin,
                               const float* __restrict__ ebuf, const float* __restrict__ z,
                               float* __restrict__ out,
                               int E, int N, int Hn) {
    int t = blockIdx.x * blockDim.x + threadIdx.x;
    int total = (E + N) * Hn;
    if (t >= total) return;
    int eid = t / Hn, hh = t - eid * Hn;
    int src, dst; edge_src_dst(srcA, dstA, eid, E, src, dst);
    float coef = ebuf[t] / (z[dst * Hn + hh] + 1e-16f);
    const float4* vp = (const float4*)(hlin + ((size_t)src * Hn + hh) * 64);
    float4*       op = (float4*)(out + ((size_t)dst * Hn + hh) * 64);
#pragma unroll
    for (int q = 0; q < 16; q++) {       // C=64 -> 16 float4
        float4 v = vp[q];
        float4 r; r.x = v.x * coef; r.y = v.y * coef; r.z = v.z * coef; r.w = v.w * coef;
        atomicAdd(op + q, r);
    }
}

__global__ void bias_act(float* __restrict__ x, const float* __restrict__ b,
                         int N, int Fout, int relu) {
    int t = blockIdx.x * blockDim.x + threadIdx.x;
    if (t >= N * Fout) return;
    int j = t % Fout;
    float v = x[t] + b[j];
    if (relu) v = fmaxf(v, 0.f);
    x[t] = v;
}

__global__ void pool_kernel(const float* __restrict__ h3, const int* __restrict__ batch,
                            float* __restrict__ xg, float* __restrict__ cnt,
                            const float* __restrict__ bias, int N) {
    int t = blockIdx.x * blockDim.x + threadIdx.x;   // one per (node, channel)
    if (t >= N * 64) return;
    int n = t >> 6, c = t & 63;
    int b = batch[n];
    atomicAdd(&xg[b * 64 + c], h3[t] + bias[c]);     // fold conv3 bias here
    if (c == 0) atomicAdd(&cnt[b], 1.f);
}

__global__ void pool_div(float* __restrict__ xg, const float* __restrict__ cnt, int B) {
    int t = blockIdx.x * blockDim.x + threadIdx.x;
    if (t >= B * 64) return;
    xg[t] /= fmaxf(cnt[t >> 6], 1.f);
}

__global__ void bias_ln(const float* __restrict__ y, const float* __restrict__ bias,
                        const float* __restrict__ g, const float* __restrict__ be,
                        float* __restrict__ out, int Fn) {
    __shared__ float red[256];
    int b = blockIdx.x, j = threadIdx.x;
    float v = y[(size_t)b * Fn + j] + bias[j];
    red[j] = v; __syncthreads();
#pragma unroll
    for (int s = 128; s > 0; s >>= 1) { if (j < s) red[j] += red[j + s]; __syncthreads(); }
    float mu = red[0] * (1.f / 256.f);
    __syncthreads();
    float dv = v - mu;
    red[j] = dv * dv; __syncthreads();
#pragma unroll
    for (int s = 128; s > 0; s >>= 1) { if (j < s) red[j] += red[j + s]; __syncthreads(); }
    float var = red[0] * (1.f / 256.f);
    out[(size_t)b * Fn + j] = dv * rsqrtf(var + 1e-5f) * g[j] + be[j];
}

// ---------------- host orchestration ---------------------------------------
// Xin may need (abias, arelu) applied on the fly (fused epilogue of prev layer).
static void gat_layer(const float* Xin, const float* abias, int arelu,
                      int Fin, int Hn,
                      const float* W, const float* asrc, const float* adst,
                      const int* srcA, const int* dstA, int N, int E,
                      float* hlin, float* outagg,
                      float* als, float* ald, float* m, float* z, float* ebuf) {
    int Fout = Hn * 64;
    launch_sgemm(Xin, W, hlin, N, Fin, Fout, abias, arelu);
    attn_logits<<<cdiv((long long)N * Hn * 32, 256), 256>>>(hlin, asrc, adst, als, ald, N, Hn, 64);
    fill_kernel<<<cdiv(N * Hn, 256), 256>>>(m, -INFINITY, N * Hn);
    cudaMemsetAsync(z, 0, (size_t)N * Hn * sizeof(float));
    cudaMemsetAsync(outagg, 0, (size_t)N * Fout * sizeof(float));
    int tot = (E + N) * Hn;
    edge_logits_max<<<cdiv(tot, 256), 256>>>(srcA, dstA, als, ald, ebuf, m, E, N, Hn);
    edge_exp_sum<<<cdiv(tot, 256), 256>>>(dstA, m, ebuf, z, E, N, Hn);
    edge_aggregate<<<cdiv(tot, 256), 256>>>(srcA, dstA, hlin, ebuf, z, outagg, E, N, Hn);
}

extern "C" void kernel_launch(void* const* d_in, const int* in_sizes, int n_in,
                              void* d_out, int out_size) {
    const float* x      = (const float*)d_in[0];
    const void*  ei_raw = d_in[1];
    const void*  b_raw  = d_in[2];
    const float* W1  = (const float*)d_in[3];
    const float* as1 = (const float*)d_in[4];
    const float* ad1 = (const float*)d_in[5];
    const float* b1  = (const float*)d_in[6];
    const float* W2  = (const float*)d_in[7];
    const float* as2 = (const float*)d_in[8];
    const float* ad2 = (const float*)d_in[9];
    const float* b2  = (const float*)d_in[10];
    const float* W3  = (const float*)d_in[11];
    const float* as3 = (const float*)d_in[12];
    const float* ad3 = (const float*)d_in[13];
    const float* b3  = (const float*)d_in[14];
    const float* Wm1 = (const float*)d_in[15];
    const float* bm1 = (const float*)d_in[16];
    const float* Wm2 = (const float*)d_in[17];
    const float* bm2 = (const float*)d_in[18];
    const float* g2  = (const float*)d_in[19];
    const float* be2 = (const float*)d_in[20];

    int N = in_sizes[0] / 32;
    int E = in_sizes[1] / 2;
    int B = out_size / 256;

    float *bufA, *bufB, *als, *ald, *m, *z, *ebuf, *xg, *cnt, *y1, *y2;
    int *srcA, *dstA, *batch;
    cudaGetSymbolAddress((void**)&bufA, g_bufA);
    cudaGetSymbolAddress((void**)&bufB, g_bufB);
    cudaGetSymbolAddress((void**)&als,  g_als);
    cudaGetSymbolAddress((void**)&ald,  g_ald);
    cudaGetSymbolAddress((void**)&m,    g_m);
    cudaGetSymbolAddress((void**)&z,    g_z);
    cudaGetSymbolAddress((void**)&ebuf, g_e);
    cudaGetSymbolAddress((void**)&xg,   g_xg);
    cudaGetSymbolAddress((void**)&cnt,  g_cnt);
    cudaGetSymbolAddress((void**)&y1,   g_y1);
    cudaGetSymbolAddress((void**)&y2,   g_y2);
    cudaGetSymbolAddress((void**)&srcA, g_src);
    cudaGetSymbolAddress((void**)&dstA, g_dst);
    cudaGetSymbolAddress((void**)&batch, g_batch);

    detect_dtype<<<1, 1>>>(ei_raw, E, N);
    convert_ei<<<cdiv(E, 256), 256>>>(ei_raw, srcA, dstA, E);
    convert_batch<<<cdiv(N, 256), 256>>>(b_raw, batch, N);

    // conv1: x(N,32) -> bufA(hlin) -> agg bufB   (raw sum; bias+relu fused into conv2 gemm)
    gat_layer(x,    nullptr, 0, 32,  4, W1, as1, ad1, srcA, dstA, N, E,
              bufA, bufB, als, ald, m, z, ebuf);
    // conv2: act(bufB + b1) -> bufA -> agg bufB  (bias+relu fused into conv3 gemm)
    gat_layer(bufB, b1, 1, 256, 4, W2, as2, ad2, srcA, dstA, N, E,
              bufA, bufB, als, ald, m, z, ebuf);
    // conv3: act(bufB + b2) -> bufA -> agg bufB  (b3 folded into pool)
    gat_layer(bufB, b2, 1, 256, 1, W3, as3, ad3, srcA, dstA, N, E,
              bufA, bufB, als, ald, m, z, ebuf);

    // global mean pool (adds b3 per channel)
    cudaMemsetAsync(xg, 0, (size_t)B * 64 * sizeof(float));
    cudaMemsetAsync(cnt, 0, (size_t)B * sizeof(float));
    pool_kernel<<<cdiv((long long)N * 64, 256), 256>>>(bufB, batch, xg, cnt, b3, N);
    pool_div<<<cdiv(B * 64, 256), 256>>>(xg, cnt, B);

    // MLP head: y1 = xg @ Wm1 ; y2 = relu(y1+bm1) @ Wm2 ; out = LN(y2+bm2)
    launch_sgemm(xg, Wm1, y1, B, 64, 256, nullptr, 0);
    launch_sgemm(y1, Wm2, y2, B, 256, 256, bm1, 1);
    bias_ln<<<B, 256>>>(y2, bm2, g2, be2, (float*)d_out, 256);
}

// round 4
// speedup vs baseline: 1.8505x; 1.5730x over previous
#include <cuda_runtime.h>
#include <math.h>
#include <stdint.h>

#define MAXN 50000
#define MAXE 500000
#define HMAX 4
#define HC_MAX 256
#define BMAX 1000
#define SCAN_T 1024

// ---------------- scratch ----------------------------------------------------
static __device__ __align__(16) float g_bufA[(size_t)MAXN * HC_MAX];
static __device__ __align__(16) float g_bufB[(size_t)MAXN * HC_MAX];
static __device__ float g_als[(size_t)MAXN * HMAX];
static __device__ float g_ald[(size_t)MAXN * HMAX];
static __device__ __align__(16) float g_xg[(size_t)BMAX * 64];
static __device__ float g_cnt[BMAX];
static __device__ __align__(16) float g_y1[(size_t)BMAX * 256];
static __device__ __align__(16) float g_y2[(size_t)BMAX * 256];
static __device__ int   g_src[MAXE];
static __device__ int   g_dst[MAXE];
static __device__ int   g_batch[MAXN];
static __device__ int   g_deg[MAXN];
static __device__ int   g_excl[MAXN];
static __device__ int   g_bsum[SCAN_T];
static __device__ int   g_rowptr[MAXN + 1];
static __device__ int   g_cursor[MAXN];
static __device__ int   g_csrc[MAXE];
static __device__ int   g_is64;

static inline int cdiv(long long a, long long b) { return (int)((a + b - 1) / b); }

// ---------------- dtype probe + index conversion ----------------------------
__global__ void detect_dtype(const void* ei_raw, int E, int N) {
    const long long* p = (const long long*)ei_raw;
    int k = E < 256 ? E : 256;
    int ok = 1;
    for (int i = 0; i < k; i++) {
        long long v = p[i];
        if (v < 0 || v >= N) { ok = 0; break; }
    }
    g_is64 = ok;
}

__global__ void convert_ei(const void* ei_raw, int* __restrict__ src,
                           int* __restrict__ dst, int E) {
    int i = blockIdx.x * blockDim.x + threadIdx.x;
    if (i >= E) return;
    if (g_is64) {
        const long long* p = (const long long*)ei_raw;
        src[i] = (int)p[i];
        dst[i] = (int)p[E + i];
    } else {
        const int* p = (const int*)ei_raw;
        src[i] = p[i];
        dst[i] = p[E + i];
    }
}

__global__ void convert_batch(const void* b_raw, int* __restrict__ out, int N) {
    int i = blockIdx.x * blockDim.x + threadIdx.x;
    if (i >= N) return;
    if (g_is64) out[i] = (int)((const long long*)b_raw)[i];
    else        out[i] = ((const int*)b_raw)[i];
}

// ---------------- CSR build --------------------------------------------------
__global__ void hist_kernel(const int* __restrict__ dstA, int* __restrict__ deg, int E) {
    int i = blockIdx.x * blockDim.x + threadIdx.x;
    if (i < E) atomicAdd(&deg[dstA[i]], 1);
}

__global__ void scan1(const int* __restrict__ deg, int* __restrict__ excl,
                      int* __restrict__ bsum, int n) {
    __shared__ int s[SCAN_T];
    int i = blockIdx.x * SCAN_T + threadIdx.x;
    int v = (i < n) ? deg[i] : 0;
    s[threadIdx.x] = v; __syncthreads();
    for (int off = 1; off < SCAN_T; off <<= 1) {
        int t = (threadIdx.x >= off) ? s[threadIdx.x - off] : 0;
        __syncthreads();
        s[threadIdx.x] += t;
        __syncthreads();
    }
    if (i < n) excl[i] = s[threadIdx.x] - v;
    if (threadIdx.x == SCAN_T - 1) bsum[blockIdx.x] = s[SCAN_T - 1];
}

__global__ void scan2(int* __restrict__ bsum, int nb) {
    __shared__ int s[SCAN_T];
    int v = (threadIdx.x < nb) ? bsum[threadIdx.x] : 0;
    s[threadIdx.x] = v; __syncthreads();
    for (int off = 1; off < SCAN_T; off <<= 1) {
        int t = (threadIdx.x >= off) ? s[threadIdx.x - off] : 0;
        __syncthreads();
        s[threadIdx.x] += t;
        __syncthreads();
    }
    if (threadIdx.x < nb) bsum[threadIdx.x] = s[threadIdx.x] - v;
}

__global__ void scan3(const int* __restrict__ excl, const int* __restrict__ bsum,
                      int* __restrict__ rowptr, int n, int E) {
    int i = blockIdx.x * blockDim.x + threadIdx.x;
    if (i < n) rowptr[i] = excl[i] + bsum[i / SCAN_T];
    if (i == 0) rowptr[n] = E;
}

__global__ void scatter_kernel(const int* __restrict__ srcA, const int* __restrict__ dstA,
                               int* __restrict__ cursor, int* __restrict__ csrc, int E) {
    int i = blockIdx.x * blockDim.x + threadIdx.x;
    if (i >= E) return;
    int pos = atomicAdd(&cursor[dstA[i]], 1);
    csrc[pos] = srcA[i];
}

// ---------------- tiled SGEMM (BM=BN=128, BK=8, 8x8/thread) ------------------
// out[N,Fout] = act(X + abias)[N,Fin] @ W[Fin,Fout]
#define APAD 136
__global__ void sgemm128(const float* __restrict__ X, const float* __restrict__ W,
                         float* __restrict__ out, int N, int Fin, int Fout,
                         const float* __restrict__ abias, int arelu) {
    __shared__ float As[8][APAD];
    __shared__ float Bs[8][APAD];
    const int tx = threadIdx.x;            // 256 threads
    const int n0 = blockIdx.x * 128;
    const int j0 = blockIdx.y * 128;
    const int tcol = tx & 15;              // 0..15
    const int trow = tx >> 4;              // 0..15
    float acc[8][8];
#pragma unroll
    for (int i = 0; i < 8; i++)
#pragma unroll
        for (int j = 0; j < 8; j++) acc[i][j] = 0.f;

    const int ar  = tx >> 1;               // A load: row 0..127
    const int ac4 = tx & 1;                // k-quad 0..1
    const int br  = tx >> 5;               // B load: k row 0..7
    const int bc4 = tx & 31;               // col-quad 0..31

    for (int k0 = 0; k0 < Fin; k0 += 8) {
        int n = n0 + ar;
        float4 av = make_float4(0.f, 0.f, 0.f, 0.f);
        if (n < N) {
            av = *(const float4*)&X[(size_t)n * Fin + k0 + ac4 * 4];
            if (abias) {
                const float4 b = *(const float4*)&abias[k0 + ac4 * 4];
                av.x += b.x; av.y += b.y; av.z += b.z; av.w += b.w;
                if (arelu) {
                    av.x = fmaxf(av.x, 0.f); av.y = fmaxf(av.y, 0.f);
                    av.z = fmaxf(av.z, 0.f); av.w = fmaxf(av.w, 0.f);
                }
            }
        }
        As[ac4 * 4 + 0][ar] = av.x;
        As[ac4 * 4 + 1][ar] = av.y;
        As[ac4 * 4 + 2][ar] = av.z;
        As[ac4 * 4 + 3][ar] = av.w;
        *(float4*)&Bs[br][bc4 * 4] =
            *(const float4*)&W[(size_t)(k0 + br) * Fout + j0 + bc4 * 4];
        __syncthreads();
#pragma unroll
        for (int k = 0; k < 8; k++) {
            float4 a0 = *(const float4*)&As[k][trow * 8];
            float4 a1 = *(const float4*)&As[k][trow * 8 + 4];
            float4 b0 = *(const float4*)&Bs[k][tcol * 8];
            float4 b1 = *(const float4*)&Bs[k][tcol * 8 + 4];
            float a[8] = {a0.x, a0.y, a0.z, a0.w, a1.x, a1.y, a1.z, a1.w};
            float b[8] = {b0.x, b0.y, b0.z, b0.w, b1.x, b1.y, b1.z, b1.w};
#pragma unroll
            for (int i = 0; i < 8; i++)
#pragma unroll
                for (int j = 0; j < 8; j++) acc[i][j] += a[i] * b[j];
        }
        __syncthreads();
    }
#pragma unroll
    for (int i = 0; i < 8; i++) {
        int n = n0 + trow * 8 + i;
        if (n >= N) continue;
        *(float4*)&out[(size_t)n * Fout + j0 + tcol * 8] =
            make_float4(acc[i][0], acc[i][1], acc[i][2], acc[i][3]);
        *(float4*)&out[(size_t)n * Fout + j0 + tcol * 8 + 4] =
            make_float4(acc[i][4], acc[i][5], acc[i][6], acc[i][7]);
    }
}

// Narrow variant for Fout=64: BM=128, BN=64, BK=16, 8x4/thread.
template <int BM, int BN, int BK, int TM, int TN>
__global__ void sgemm_narrow(const float* __restrict__ X, const float* __restrict__ W,
                             float* __restrict__ out, int N, int Fin, int Fout,
                             const float* __restrict__ abias, int arelu) {
    __shared__ float As[BK][BM];
    __shared__ float Bs[BK][BN];
    const int tx = threadIdx.x;
    const int n0 = blockIdx.x * BM;
    const int j0 = blockIdx.y * BN;
    const int tcol = tx % (BN / TN);
    const int trow = tx / (BN / TN);
    float acc[TM][TN];
#pragma unroll
    for (int i = 0; i < TM; i++)
#pragma unroll
        for (int j = 0; j < TN; j++) acc[i][j] = 0.f;

    for (int k0 = 0; k0 < Fin; k0 += BK) {
#pragma unroll
        for (int i = tx; i < BM * BK / 4; i += 256) {
            int r = i / (BK / 4), c4 = i % (BK / 4);
            int n = n0 + r;
            float4 v = make_float4(0.f, 0.f, 0.f, 0.f);
            if (n < N) {
                v = *(const float4*)&X[(size_t)n * Fin + k0 + c4 * 4];
                if (abias) {
                    const float4 b = *(const float4*)&abias[k0 + c4 * 4];
                    v.x += b.x; v.y += b.y; v.z += b.z; v.w += b.w;
                    if (arelu) {
                        v.x = fmaxf(v.x, 0.f); v.y = fmaxf(v.y, 0.f);
                        v.z = fmaxf(v.z, 0.f); v.w = fmaxf(v.w, 0.f);
                    }
                }
            }
            As[c4 * 4 + 0][r] = v.x; As[c4 * 4 + 1][r] = v.y;
            As[c4 * 4 + 2][r] = v.z; As[c4 * 4 + 3][r] = v.w;
        }
#pragma unroll
        for (int i = tx; i < BK * BN / 4; i += 256) {
            int r = i / (BN / 4), c4 = i % (BN / 4);
            *(float4*)&Bs[r][c4 * 4] =
                *(const float4*)&W[(size_t)(k0 + r) * Fout + j0 + c4 * 4];
        }
        __syncthreads();
#pragma unroll
        for (int k = 0; k < BK; k++) {
            float a[TM], b[TN];
#pragma unroll
            for (int i = 0; i < TM; i++) a[i] = As[k][trow * TM + i];
#pragma unroll
            for (int j = 0; j < TN; j++) b[j] = Bs[k][tcol * TN + j];
#pragma unroll
            for (int i = 0; i < TM; i++)
#pragma unroll
                for (int j = 0; j < TN; j++) acc[i][j] += a[i] * b[j];
        }
        __syncthreads();
    }
#pragma unroll
    for (int i = 0; i < TM; i++) {
        int n = n0 + trow * TM + i;
        if (n >= N) continue;
#pragma unroll
        for (int j4 = 0; j4 < TN / 4; j4++)
            *(float4*)&out[(size_t)n * Fout + j0 + tcol * TN + j4 * 4] =
                make_float4(acc[i][j4 * 4 + 0], acc[i][j4 * 4 + 1],
                            acc[i][j4 * 4 + 2], acc[i][j4 * 4 + 3]);
    }
}

static void launch_sgemm(const float* X, const float* W, float* out,
                         int N, int Fin, int Fout, const float* abias, int arelu) {
    if (Fout % 128 == 0) {
        dim3 grid(cdiv(N, 128), Fout / 128);
        sgemm128<<<grid, 256>>>(X, W, out, N, Fin, Fout, abias, arelu);
    } else {
        dim3 grid(cdiv(N, 128), Fout / 64);
        sgemm_narrow<128, 64, 16, 8, 4><<<grid, 256>>>(X, W, out, N, Fin, Fout, abias, arelu);
    }
}

// ---------------- attention logits -------------------------------------------
__global__ void attn_logits(const float* __restrict__ h, const float* __restrict__ a_src,
                            const float* __restrict__ a_dst,
                            float* __restrict__ als, float* __restrict__ ald,
                            int N, int Hn) {
    int wid = (blockIdx.x * blockDim.x + threadIdx.x) >> 5;
    int lane = threadIdx.x & 31;
    if (wid >= N * Hn) return;
    int n = wid / Hn, hh = wid - n * Hn;
    const float* row = h + ((size_t)n * Hn + hh) * 64;
    float v0 = row[lane], v1 = row[lane + 32];
    float s = v0 * a_src[hh * 64 + lane] + v1 * a_src[hh * 64 + lane + 32];
    float d = v0 * a_dst[hh * 64 + lane] + v1 * a_dst[hh * 64 + lane + 32];
#pragma unroll
    for (int o = 16; o > 0; o >>= 1) {
        s += __shfl_down_sync(0xFFFFFFFFu, s, o);
        d += __shfl_down_sync(0xFFFFFFFFu, d, o);
    }
    if (lane == 0) { als[wid] = s; ald[wid] = d; }
}

// ---------------- fused GAT softmax + aggregation ----------------------------
// One warp per (dst, head). Online softmax over CSR in-edges + self loop.
__global__ void gat_fused(const int* __restrict__ rowptr, const int* __restrict__ csrc,
                          const float* __restrict__ hlin,
                          const float* __restrict__ als, const float* __restrict__ ald,
                          float* __restrict__ out, int N, int Hn) {
    int wid = (blockIdx.x * blockDim.x + threadIdx.x) >> 5;
    int lane = threadIdx.x & 31;
    if (wid >= N * Hn) return;
    int n = wid / Hn, hh = wid - n * Hn;
    float aldd = ald[n * Hn + hh];
    // self loop initializes the online-softmax state
    float m = als[n * Hn + hh] + aldd;
    m = (m > 0.f) ? m : 0.2f * m;
    const float* hrow = hlin + ((size_t)n * Hn + hh) * 64;
    float acc0 = hrow[lane], acc1 = hrow[lane + 32];
    float z = 1.f;
    int beg = rowptr[n], end = rowptr[n + 1];
    for (int k = beg; k < end; k++) {
        int src = csrc[k];
        float e = als[src * Hn + hh] + aldd;
        e = (e > 0.f) ? e : 0.2f * e;
        float mn = fmaxf(m, e);
        float s = __expf(m - mn);
        float p = __expf(e - mn);
        const float* hs = hlin + ((size_t)src * Hn + hh) * 64;
        acc0 = acc0 * s + p * hs[lane];
        acc1 = acc1 * s + p * hs[lane + 32];
        z = z * s + p;
        m = mn;
    }
    float inv = 1.f / (z + 1e-16f);
    float* orow = out + ((size_t)n * Hn + hh) * 64;
    orow[lane]      = acc0 * inv;
    orow[lane + 32] = acc1 * inv;
}

// ---------------- pooling + LN -----------------------------------------------
__global__ void pool_kernel(const float* __restrict__ h3, const int* __restrict__ batch,
                            float* __restrict__ xg, float* __restrict__ cnt,
                            const float* __restrict__ bias, int N) {
    int t = blockIdx.x * blockDim.x + threadIdx.x;
    if (t >= N * 64) return;
    int n = t >> 6, c = t & 63;
    int b = batch[n];
    atomicAdd(&xg[b * 64 + c], h3[t] + bias[c]);
    if (c == 0) atomicAdd(&cnt[b], 1.f);
}

__global__ void pool_div(float* __restrict__ xg, const float* __restrict__ cnt, int B) {
    int t = blockIdx.x * blockDim.x + threadIdx.x;
    if (t >= B * 64) return;
    xg[t] /= fmaxf(cnt[t >> 6], 1.f);
}

__global__ void bias_ln(const float* __restrict__ y, const float* __restrict__ bias,
                        const float* __restrict__ g, const float* __restrict__ be,
                        float* __restrict__ out, int Fn) {
    __shared__ float red[256];
    int b = blockIdx.x, j = threadIdx.x;
    float v = y[(size_t)b * Fn + j] + bias[j];
    red[j] = v; __syncthreads();
#pragma unroll
    for (int s = 128; s > 0; s >>= 1) { if (j < s) red[j] += red[j + s]; __syncthreads(); }
    float mu = red[0] * (1.f / 256.f);
    __syncthreads();
    float dv = v - mu;
    red[j] = dv * dv; __syncthreads();
#pragma unroll
    for (int s = 128; s > 0; s >>= 1) { if (j < s) red[j] += red[j + s]; __syncthreads(); }
    float var = red[0] * (1.f / 256.f);
    out[(size_t)b * Fn + j] = dv * rsqrtf(var + 1e-5f) * g[j] + be[j];
}

// ---------------- host orchestration ---------------------------------------
static void gat_layer(const float* Xin, const float* abias, int arelu,
                      int Fin, int Hn,
                      const float* W, const float* asrc, const float* adst,
                      const int* rowptr, const int* csrc, int N,
                      float* hlin, float* outagg, float* als, float* ald) {
    int Fout = Hn * 64;
    launch_sgemm(Xin, W, hlin, N, Fin, Fout, abias, arelu);
    attn_logits<<<cdiv((long long)N * Hn * 32, 256), 256>>>(hlin, asrc, adst, als, ald, N, Hn);
    gat_fused<<<cdiv((long long)N * Hn * 32, 256), 256>>>(rowptr, csrc, hlin, als, ald,
                                                          outagg, N, Hn);
}

extern "C" void kernel_launch(void* const* d_in, const int* in_sizes, int n_in,
                              void* d_out, int out_size) {
    const float* x      = (const float*)d_in[0];
    const void*  ei_raw = d_in[1];
    const void*  b_raw  = d_in[2];
    const float* W1  = (const float*)d_in[3];
    const float* as1 = (const float*)d_in[4];
    const float* ad1 = (const float*)d_in[5];
    const float* b1  = (const float*)d_in[6];
    const float* W2  = (const float*)d_in[7];
    const float* as2 = (const float*)d_in[8];
    const float* ad2 = (const float*)d_in[9];
    const float* b2  = (const float*)d_in[10];
    const float* W3  = (const float*)d_in[11];
    const float* as3 = (const float*)d_in[12];
    const float* ad3 = (const float*)d_in[13];
    const float* b3  = (const float*)d_in[14];
    const float* Wm1 = (const float*)d_in[15];
    const float* bm1 = (const float*)d_in[16];
    const float* Wm2 = (const float*)d_in[17];
    const float* bm2 = (const float*)d_in[18];
    const float* g2  = (const float*)d_in[19];
    const float* be2 = (const float*)d_in[20];

    int N = in_sizes[0] / 32;
    int E = in_sizes[1] / 2;
    int B = out_size / 256;

    float *bufA, *bufB, *als, *ald, *xg, *cnt, *y1, *y2;
    int *srcA, *dstA, *batch, *deg, *excl, *bsum, *rowptr, *cursor, *csrc;
    cudaGetSymbolAddress((void**)&bufA, g_bufA);
    cudaGetSymbolAddress((void**)&bufB, g_bufB);
    cudaGetSymbolAddress((void**)&als,  g_als);
    cudaGetSymbolAddress((void**)&ald,  g_ald);
    cudaGetSymbolAddress((void**)&xg,   g_xg);
    cudaGetSymbolAddress((void**)&cnt,  g_cnt);
    cudaGetSymbolAddress((void**)&y1,   g_y1);
    cudaGetSymbolAddress((void**)&y2,   g_y2);
    cudaGetSymbolAddress((void**)&srcA, g_src);
    cudaGetSymbolAddress((void**)&dstA, g_dst);
    cudaGetSymbolAddress((void**)&batch, g_batch);
    cudaGetSymbolAddress((void**)&deg,  g_deg);
    cudaGetSymbolAddress((void**)&excl, g_excl);
    cudaGetSymbolAddress((void**)&bsum, g_bsum);
    cudaGetSymbolAddress((void**)&rowptr, g_rowptr);
    cudaGetSymbolAddress((void**)&cursor, g_cursor);
    cudaGetSymbolAddress((void**)&csrc, g_csrc);

    // dtype normalize
    detect_dtype<<<1, 1>>>(ei_raw, E, N);
    convert_ei<<<cdiv(E, 256), 256>>>(ei_raw, srcA, dstA, E);
    convert_batch<<<cdiv(N, 256), 256>>>(b_raw, batch, N);

    // CSR by dst (self loops handled inside gat_fused)
    cudaMemsetAsync(deg, 0, (size_t)N * sizeof(int));
    hist_kernel<<<cdiv(E, 256), 256>>>(dstA, deg, E);
    int nb = cdiv(N, SCAN_T);
    scan1<<<nb, SCAN_T>>>(deg, excl, bsum, N);
    scan2<<<1, SCAN_T>>>(bsum, nb);
    scan3<<<cdiv(N + 1, 256), 256>>>(excl, bsum, rowptr, N, E);
    cudaMemcpyAsync(cursor, rowptr, (size_t)N * sizeof(int), cudaMemcpyDeviceToDevice);
    scatter_kernel<<<cdiv(E, 256), 256>>>(srcA, dstA, cursor, csrc, E);

    // conv1: x(N,32) -> bufA(hlin) -> bufB (bias+relu fused into conv2's A load)
    gat_layer(x,    nullptr, 0, 32,  4, W1, as1, ad1, rowptr, csrc, N, bufA, bufB, als, ald);
    // conv2
    gat_layer(bufB, b1, 1, 256, 4, W2, as2, ad2, rowptr, csrc, N, bufA, bufB, als, ald);
    // conv3 (H=1)
    gat_layer(bufB, b2, 1, 256, 1, W3, as3, ad3, rowptr, csrc, N, bufA, bufB, als, ald);

    // global mean pool (+b3)
    cudaMemsetAsync(xg, 0, (size_t)B * 64 * sizeof(float));
    cudaMemsetAsync(cnt, 0, (size_t)B * sizeof(float));
    pool_kernel<<<cdiv((long long)N * 64, 256), 256>>>(bufB, batch, xg, cnt, b3, N);
    pool_div<<<cdiv(B * 64, 256), 256>>>(xg, cnt, B);

    // MLP head
    launch_sgemm(xg, Wm1, y1, B, 64, 256, nullptr, 0);
    launch_sgemm(y1, Wm2, y2, B, 256, 256, bm1, 1);
    bias_ln<<<B, 256>>>(y2, bm2, g2, be2, (float*)d_out, 256);
}

// round 5
// speedup vs baseline: 2.4859x; 1.3434x over previous
#include <cuda_runtime.h>
#include <math.h>
#include <stdint.h>

#define MAXN 50000
#define MAXE 500000
#define HMAX 4
#define HC_MAX 256
#define BMAX 1000
#define SCAN_T 1024

// ---------------- scratch ----------------------------------------------------
static __device__ __align__(16) float g_bufA[(size_t)MAXN * HC_MAX];
static __device__ __align__(16) float g_bufB[(size_t)MAXN * HC_MAX];
static __device__ float g_als[(size_t)MAXN * HMAX];
static __device__ float g_ald[(size_t)MAXN * HMAX];
static __device__ __align__(16) float g_xg[(size_t)BMAX * 64];
static __device__ float g_cnt[BMAX];
static __device__ __align__(16) float g_y1[(size_t)BMAX * 256];
static __device__ __align__(16) float g_y2[(size_t)BMAX * 256];
static __device__ int   g_src[MAXE];
static __device__ int   g_dst[MAXE];
static __device__ int   g_batch[MAXN];
static __device__ int   g_deg[MAXN];
static __device__ int   g_excl[MAXN];
static __device__ int   g_bsum[SCAN_T];
static __device__ int   g_rowptr[MAXN + 1];
static __device__ int   g_cursor[MAXN];
static __device__ int   g_csrc[MAXE];
static __device__ int   g_is64;

static inline int cdiv(long long a, long long b) { return (int)((a + b - 1) / b); }

// ---------------- dtype probe + index conversion ----------------------------
__global__ void detect_dtype(const void* ei_raw, int E, int N) {
    const long long* p = (const long long*)ei_raw;
    int k = E < 256 ? E : 256;
    int ok = 1;
    for (int i = 0; i < k; i++) {
        long long v = p[i];
        if (v < 0 || v >= N) { ok = 0; break; }
    }
    g_is64 = ok;
}

__global__ void convert_ei(const void* ei_raw, int* __restrict__ src,
                           int* __restrict__ dst, int E) {
    int i = blockIdx.x * blockDim.x + threadIdx.x;
    if (i >= E) return;
    if (g_is64) {
        const long long* p = (const long long*)ei_raw;
        src[i] = (int)p[i];
        dst[i] = (int)p[E + i];
    } else {
        const int* p = (const int*)ei_raw;
        src[i] = p[i];
        dst[i] = p[E + i];
    }
}

__global__ void convert_batch(const void* b_raw, int* __restrict__ out, int N) {
    int i = blockIdx.x * blockDim.x + threadIdx.x;
    if (i >= N) return;
    if (g_is64) out[i] = (int)((const long long*)b_raw)[i];
    else        out[i] = ((const int*)b_raw)[i];
}

// ---------------- CSR build --------------------------------------------------
__global__ void hist_kernel(const int* __restrict__ dstA, int* __restrict__ deg, int E) {
    int i = blockIdx.x * blockDim.x + threadIdx.x;
    if (i < E) atomicAdd(&deg[dstA[i]], 1);
}

__global__ void scan1(const int* __restrict__ deg, int* __restrict__ excl,
                      int* __restrict__ bsum, int n) {
    __shared__ int s[SCAN_T];
    int i = blockIdx.x * SCAN_T + threadIdx.x;
    int v = (i < n) ? deg[i] : 0;
    s[threadIdx.x] = v; __syncthreads();
    for (int off = 1; off < SCAN_T; off <<= 1) {
        int t = (threadIdx.x >= off) ? s[threadIdx.x - off] : 0;
        __syncthreads();
        s[threadIdx.x] += t;
        __syncthreads();
    }
    if (i < n) excl[i] = s[threadIdx.x] - v;
    if (threadIdx.x == SCAN_T - 1) bsum[blockIdx.x] = s[SCAN_T - 1];
}

__global__ void scan2(int* __restrict__ bsum, int nb) {
    __shared__ int s[SCAN_T];
    int v = (threadIdx.x < nb) ? bsum[threadIdx.x] : 0;
    s[threadIdx.x] = v; __syncthreads();
    for (int off = 1; off < SCAN_T; off <<= 1) {
        int t = (threadIdx.x >= off) ? s[threadIdx.x - off] : 0;
        __syncthreads();
        s[threadIdx.x] += t;
        __syncthreads();
    }
    if (threadIdx.x < nb) bsum[threadIdx.x] = s[threadIdx.x] - v;
}

__global__ void scan3(const int* __restrict__ excl, const int* __restrict__ bsum,
                      int* __restrict__ rowptr, int n, int E) {
    int i = blockIdx.x * blockDim.x + threadIdx.x;
    if (i < n) rowptr[i] = excl[i] + bsum[i / SCAN_T];
    if (i == 0) rowptr[n] = E;
}

__global__ void scatter_kernel(const int* __restrict__ srcA, const int* __restrict__ dstA,
                               int* __restrict__ cursor, int* __restrict__ csrc, int E) {
    int i = blockIdx.x * blockDim.x + threadIdx.x;
    if (i >= E) return;
    int pos = atomicAdd(&cursor[dstA[i]], 1);
    csrc[pos] = srcA[i];
}

// ---------------- TF32 tensor-core GEMM --------------------------------------
// out[N,Fout] = act(X + abias) @ W.  BM=128, BK=32, 8 warps / 256 threads.
// BN=128: warps 2x4, warp tile 64x32 (MI=4,NI=4).
// BN=64 : warps 4x2, warp tile 32x32 (MI=2,NI=4).
__device__ __forceinline__ uint32_t f2tf32(float x) {
    uint32_t r; asm("cvt.rna.tf32.f32 %0, %1;" : "=r"(r) : "f"(x)); return r;
}

__device__ __forceinline__ void mma_tf32(float* c, const uint32_t* a, const uint32_t* b) {
    asm volatile(
        "mma.sync.aligned.m16n8k8.row.col.f32.tf32.tf32.f32 "
        "{%0,%1,%2,%3}, {%4,%5,%6,%7}, {%8,%9}, {%0,%1,%2,%3};"
        : "+f"(c[0]), "+f"(c[1]), "+f"(c[2]), "+f"(c[3])
        : "r"(a[0]), "r"(a[1]), "r"(a[2]), "r"(a[3]), "r"(b[0]), "r"(b[1]));
}

template <int BN, int WR, int WC, int MI>
__global__ void tf32_gemm(const float* __restrict__ X, const float* __restrict__ W,
                          float* __restrict__ out, int N, int Fin, int Fout,
                          const float* __restrict__ abias, int arelu) {
    constexpr int BM = 128, BK = 32, NI = 4;
    constexpr int WM = BM / WR;            // == MI*16
    constexpr int WN = BN / WC;            // == 32
    __shared__ uint32_t As[BK][BM + 4];    // As[k][m]
    __shared__ uint32_t Bs[BK][BN + 4];    // Bs[k][n]
    const int tx = threadIdx.x;
    const int n0 = blockIdx.x * BM;
    const int j0 = blockIdx.y * BN;
    const int w  = tx >> 5;
    const int lane = tx & 31;
    const int g = lane >> 2;               // groupID 0..7
    const int q = lane & 3;                // threadID_in_group 0..3
    const int wr = w / WC, wc = w % WC;
    const int m0w = wr * WM, n0w = wc * WN;

    float acc[MI][NI][4];
#pragma unroll
    for (int mi = 0; mi < MI; mi++)
#pragma unroll
        for (int ni = 0; ni < NI; ni++)
#pragma unroll
            for (int t = 0; t < 4; t++) acc[mi][ni][t] = 0.f;

    // A-load mapping: 2 threads per row, 4 float4 each.
    const int ar  = tx >> 1;
    const int ac0 = (tx & 1) * 16;
    // B-load mapping: 8 threads per k-row, BN/32 float4 each.
    const int br  = tx >> 3;
    const int bc0 = (tx & 7) * (BN / 8);

    for (int k0 = 0; k0 < Fin; k0 += BK) {
        {   // A tile -> As[k][m], bias+relu fused, cvt tf32
            int n = n0 + ar;
#pragma unroll
            for (int i = 0; i < 4; i++) {
                int c = ac0 + i * 4;
                float4 v = make_float4(0.f, 0.f, 0.f, 0.f);
                if (n < N) {
                    v = *(const float4*)&X[(size_t)n * Fin + k0 + c];
                    if (abias) {
                        const float4 b = *(const float4*)&abias[k0 + c];
                        v.x += b.x; v.y += b.y; v.z += b.z; v.w += b.w;
                        if (arelu) {
                            v.x = fmaxf(v.x, 0.f); v.y = fmaxf(v.y, 0.f);
                            v.z = fmaxf(v.z, 0.f); v.w = fmaxf(v.w, 0.f);
                        }
                    }
                }
                As[c + 0][ar] = f2tf32(v.x);
                As[c + 1][ar] = f2tf32(v.y);
                As[c + 2][ar] = f2tf32(v.z);
                As[c + 3][ar] = f2tf32(v.w);
            }
        }
        {   // B tile -> Bs[k][n]
#pragma unroll
            for (int i = 0; i < BN / 32; i++) {
                int c = bc0 + i * 4;
                float4 v = *(const float4*)&W[(size_t)(k0 + br) * Fout + j0 + c];
                Bs[br][c + 0] = f2tf32(v.x);
                Bs[br][c + 1] = f2tf32(v.y);
                Bs[br][c + 2] = f2tf32(v.z);
                Bs[br][c + 3] = f2tf32(v.w);
            }
        }
        __syncthreads();
#pragma unroll
        for (int ks = 0; ks < BK / 8; ks++) {
            uint32_t af[MI][4], bf[NI][2];
#pragma unroll
            for (int mi = 0; mi < MI; mi++) {
                int m = m0w + mi * 16 + g;
                af[mi][0] = As[ks * 8 + q][m];
                af[mi][1] = As[ks * 8 + q][m + 8];
                af[mi][2] = As[ks * 8 + q + 4][m];
                af[mi][3] = As[ks * 8 + q + 4][m + 8];
            }
#pragma unroll
            for (int ni = 0; ni < NI; ni++) {
                int c = n0w + ni * 8 + g;
                bf[ni][0] = Bs[ks * 8 + q][c];
                bf[ni][1] = Bs[ks * 8 + q + 4][c];
            }
#pragma unroll
            for (int mi = 0; mi < MI; mi++)
#pragma unroll
                for (int ni = 0; ni < NI; ni++)
                    mma_tf32(acc[mi][ni], af[mi], bf[ni]);
        }
        __syncthreads();
    }
    // epilogue: c0=(g,2q), c1=(g,2q+1), c2=(g+8,2q), c3=(g+8,2q+1)
#pragma unroll
    for (int mi = 0; mi < MI; mi++) {
        int r0 = n0 + m0w + mi * 16 + g;
        int r1 = r0 + 8;
#pragma unroll
        for (int ni = 0; ni < NI; ni++) {
            int c = j0 + n0w + ni * 8 + 2 * q;
            if (r0 < N) *(float2*)&out[(size_t)r0 * Fout + c] =
                make_float2(acc[mi][ni][0], acc[mi][ni][1]);
            if (r1 < N) *(float2*)&out[(size_t)r1 * Fout + c] =
                make_float2(acc[mi][ni][2], acc[mi][ni][3]);
        }
    }
}

static void launch_sgemm(const float* X, const float* W, float* out,
                         int N, int Fin, int Fout, const float* abias, int arelu) {
    if (Fout % 128 == 0) {
        dim3 grid(cdiv(N, 128), Fout / 128);
        tf32_gemm<128, 2, 4, 4><<<grid, 256>>>(X, W, out, N, Fin, Fout, abias, arelu);
    } else {
        dim3 grid(cdiv(N, 128), Fout / 64);
        tf32_gemm<64, 4, 2, 2><<<grid, 256>>>(X, W, out, N, Fin, Fout, abias, arelu);
    }
}

// ---------------- attention logits -------------------------------------------
__global__ void attn_logits(const float* __restrict__ h, const float* __restrict__ a_src,
                            const float* __restrict__ a_dst,
                            float* __restrict__ als, float* __restrict__ ald,
                            int N, int Hn) {
    int wid = (blockIdx.x * blockDim.x + threadIdx.x) >> 5;
    int lane = threadIdx.x & 31;
    if (wid >= N * Hn) return;
    int n = wid / Hn, hh = wid - n * Hn;
    const float* row = h + ((size_t)n * Hn + hh) * 64;
    float v0 = row[lane], v1 = row[lane + 32];
    float s = v0 * a_src[hh * 64 + lane] + v1 * a_src[hh * 64 + lane + 32];
    float d = v0 * a_dst[hh * 64 + lane] + v1 * a_dst[hh * 64 + lane + 32];
#pragma unroll
    for (int o = 16; o > 0; o >>= 1) {
        s += __shfl_down_sync(0xFFFFFFFFu, s, o);
        d += __shfl_down_sync(0xFFFFFFFFu, d, o);
    }
    if (lane == 0) { als[wid] = s; ald[wid] = d; }
}

// ---------------- fused GAT softmax + aggregation ----------------------------
__global__ void gat_fused(const int* __restrict__ rowptr, const int* __restrict__ csrc,
                          const float* __restrict__ hlin,
                          const float* __restrict__ als, const float* __restrict__ ald,
                          float* __restrict__ out, int N, int Hn) {
    int wid = (blockIdx.x * blockDim.x + threadIdx.x) >> 5;
    int lane = threadIdx.x & 31;
    if (wid >= N * Hn) return;
    int n = wid / Hn, hh = wid - n * Hn;
    float aldd = ald[n * Hn + hh];
    float m = als[n * Hn + hh] + aldd;     // self loop init
    m = (m > 0.f) ? m : 0.2f * m;
    const float* hrow = hlin + ((size_t)n * Hn + hh) * 64;
    float acc0 = hrow[lane], acc1 = hrow[lane + 32];
    float z = 1.f;
    int beg = rowptr[n], end = rowptr[n + 1];
    for (int k = beg; k < end; k++) {
        int src = csrc[k];
        float e = als[src * Hn + hh] + aldd;
        e = (e > 0.f) ? e : 0.2f * e;
        float mn = fmaxf(m, e);
        float s = __expf(m - mn);
        float p = __expf(e - mn);
        const float* hs = hlin + ((size_t)src * Hn + hh) * 64;
        acc0 = acc0 * s + p * hs[lane];
        acc1 = acc1 * s + p * hs[lane + 32];
        z = z * s + p;
        m = mn;
    }
    float inv = 1.f / (z + 1e-16f);
    float* orow = out + ((size_t)n * Hn + hh) * 64;
    orow[lane]      = acc0 * inv;
    orow[lane + 32] = acc1 * inv;
}

// ---------------- pooling + LN -----------------------------------------------
__global__ void pool_kernel(const float* __restrict__ h3, const int* __restrict__ batch,
                            float* __restrict__ xg, float* __restrict__ cnt,
                            const float* __restrict__ bias, int N) {
    int t = blockIdx.x * blockDim.x + threadIdx.x;
    if (t >= N * 64) return;
    int n = t >> 6, c = t & 63;
    int b = batch[n];
    atomicAdd(&xg[b * 64 + c], h3[t] + bias[c]);
    if (c == 0) atomicAdd(&cnt[b], 1.f);
}

__global__ void pool_div(float* __restrict__ xg, const float* __restrict__ cnt, int B) {
    int t = blockIdx.x * blockDim.x + threadIdx.x;
    if (t >= B * 64) return;
    xg[t] /= fmaxf(cnt[t >> 6], 1.f);
}

__global__ void bias_ln(const float* __restrict__ y, const float* __restrict__ bias,
                        const float* __restrict__ g, const float* __restrict__ be,
                        float* __restrict__ out, int Fn) {
    __shared__ float red[256];
    int b = blockIdx.x, j = threadIdx.x;
    float v = y[(size_t)b * Fn + j] + bias[j];
    red[j] = v; __syncthreads();
#pragma unroll
    for (int s = 128; s > 0; s >>= 1) { if (j < s) red[j] += red[j + s]; __syncthreads(); }
    float mu = red[0] * (1.f / 256.f);
    __syncthreads();
    float dv = v - mu;
    red[j] = dv * dv; __syncthreads();
#pragma unroll
    for (int s = 128; s > 0; s >>= 1) { if (j < s) red[j] += red[j + s]; __syncthreads(); }
    float var = red[0] * (1.f / 256.f);
    out[(size_t)b * Fn + j] = dv * rsqrtf(var + 1e-5f) * g[j] + be[j];
}

// ---------------- host orchestration ---------------------------------------
static void gat_layer(const float* Xin, const float* abias, int arelu,
                      int Fin, int Hn,
                      const float* W, const float* asrc, const float* adst,
                      const int* rowptr, const int* csrc, int N,
                      float* hlin, float* outagg, float* als, float* ald) {
    int Fout = Hn * 64;
    launch_sgemm(Xin, W, hlin, N, Fin, Fout, abias, arelu);
    attn_logits<<<cdiv((long long)N * Hn * 32, 256), 256>>>(hlin, asrc, adst, als, ald, N, Hn);
    gat_fused<<<cdiv((long long)N * Hn * 32, 256), 256>>>(rowptr, csrc, hlin, als, ald,
                                                          outagg, N, Hn);
}

extern "C" void kernel_launch(void* const* d_in, const int* in_sizes, int n_in,
                              void* d_out, int out_size) {
    const float* x      = (const float*)d_in[0];
    const void*  ei_raw = d_in[1];
    const void*  b_raw  = d_in[2];
    const float* W1  = (const float*)d_in[3];
    const float* as1 = (const float*)d_in[4];
    const float* ad1 = (const float*)d_in[5];
    const float* b1  = (const float*)d_in[6];
    const float* W2  = (const float*)d_in[7];
    const float* as2 = (const float*)d_in[8];
    const float* ad2 = (const float*)d_in[9];
    const float* b2  = (const float*)d_in[10];
    const float* W3  = (const float*)d_in[11];
    const float* as3 = (const float*)d_in[12];
    const float* ad3 = (const float*)d_in[13];
    const float* b3  = (const float*)d_in[14];
    const float* Wm1 = (const float*)d_in[15];
    const float* bm1 = (const float*)d_in[16];
    const float* Wm2 = (const float*)d_in[17];
    const float* bm2 = (const float*)d_in[18];
    const float* g2  = (const float*)d_in[19];
    const float* be2 = (const float*)d_in[20];

    int N = in_sizes[0] / 32;
    int E = in_sizes[1] / 2;
    int B = out_size / 256;

    float *bufA, *bufB, *als, *ald, *xg, *cnt, *y1, *y2;
    int *srcA, *dstA, *batch, *deg, *excl, *bsum, *rowptr, *cursor, *csrc;
    cudaGetSymbolAddress((void**)&bufA, g_bufA);
    cudaGetSymbolAddress((void**)&bufB, g_bufB);
    cudaGetSymbolAddress((void**)&als,  g_als);
    cudaGetSymbolAddress((void**)&ald,  g_ald);
    cudaGetSymbolAddress((void**)&xg,   g_xg);
    cudaGetSymbolAddress((void**)&cnt,  g_cnt);
    cudaGetSymbolAddress((void**)&y1,   g_y1);
    cudaGetSymbolAddress((void**)&y2,   g_y2);
    cudaGetSymbolAddress((void**)&srcA, g_src);
    cudaGetSymbolAddress((void**)&dstA, g_dst);
    cudaGetSymbolAddress((void**)&batch, g_batch);
    cudaGetSymbolAddress((void**)&deg,  g_deg);
    cudaGetSymbolAddress((void**)&excl, g_excl);
    cudaGetSymbolAddress((void**)&bsum, g_bsum);
    cudaGetSymbolAddress((void**)&rowptr, g_rowptr);
    cudaGetSymbolAddress((void**)&cursor, g_cursor);
    cudaGetSymbolAddress((void**)&csrc, g_csrc);

    // dtype normalize
    detect_dtype<<<1, 1>>>(ei_raw, E, N);
    convert_ei<<<cdiv(E, 256), 256>>>(ei_raw, srcA, dstA, E);
    convert_batch<<<cdiv(N, 256), 256>>>(b_raw, batch, N);

    // CSR by dst (self loops handled inside gat_fused)
    cudaMemsetAsync(deg, 0, (size_t)N * sizeof(int));
    hist_kernel<<<cdiv(E, 256), 256>>>(dstA, deg, E);
    int nb = cdiv(N, SCAN_T);
    scan1<<<nb, SCAN_T>>>(deg, excl, bsum, N);
    scan2<<<1, SCAN_T>>>(bsum, nb);
    scan3<<<cdiv(N + 1, 256), 256>>>(excl, bsum, rowptr, N, E);
    cudaMemcpyAsync(cursor, rowptr, (size_t)N * sizeof(int), cudaMemcpyDeviceToDevice);
    scatter_kernel<<<cdiv(E, 256), 256>>>(srcA, dstA, cursor, csrc, E);

    // conv1 .. conv3
    gat_layer(x,    nullptr, 0, 32,  4, W1, as1, ad1, rowptr, csrc, N, bufA, bufB, als, ald);
    gat_layer(bufB, b1, 1, 256, 4, W2, as2, ad2, rowptr, csrc, N, bufA, bufB, als, ald);
    gat_layer(bufB, b2, 1, 256, 1, W3, as3, ad3, rowptr, csrc, N, bufA, bufB, als, ald);

    // global mean pool (+b3)
    cudaMemsetAsync(xg, 0, (size_t)B * 64 * sizeof(float));
    cudaMemsetAsync(cnt, 0, (size_t)B * sizeof(float));
    pool_kernel<<<cdiv((long long)N * 64, 256), 256>>>(bufB, batch, xg, cnt, b3, N);
    pool_div<<<cdiv(B * 64, 256), 256>>>(xg, cnt, B);

    // MLP head
    launch_sgemm(xg, Wm1, y1, B, 64, 256, nullptr, 0);
    launch_sgemm(y1, Wm2, y2, B, 256, 256, bm1, 1);
    bias_ln<<<B, 256>>>(y2, bm2, g2, be2, (float*)d_out, 256);
}